// round 16
// baseline (speedup 1.0000x reference)
#include <cuda_runtime.h>

typedef unsigned long long u64;
typedef unsigned int u32;

#define NN 20000
#define NE 400000
#define NB 4
#define HID 256
#define OD 128
#define CHUNK 64

// YZ table in bf16 pairs: row = 512 bf16 = 256 u32 words = 1024 bytes.
// Y half (cols 0..255) has b_edge folded in.
__device__ __align__(16) u32 g_YZ[NN * 256];
__device__ float g_S[NB * HID];
__device__ int g_is_i64;

__device__ __forceinline__ u64 pk2(float lo, float hi) {
    u64 r;
    asm("mov.b64 %0, {%1, %2};" : "=l"(r) : "r"(__float_as_uint(lo)), "r"(__float_as_uint(hi)));
    return r;
}
__device__ __forceinline__ void upk2(u64 p, float &lo, float &hi) {
    unsigned a, b;
    asm("mov.b64 {%0, %1}, %2;" : "=r"(a), "=r"(b) : "l"(p));
    lo = __uint_as_float(a); hi = __uint_as_float(b);
}
__device__ __forceinline__ u64 add2(u64 a, u64 b) {
    u64 d;
    asm("add.rn.f32x2 %0, %1, %2;" : "=l"(d) : "l"(a), "l"(b));
    return d;
}
__device__ __forceinline__ u32 hadd2bf(u32 a, u32 b) {
    u32 d;
    asm("add.rn.bf16x2 %0, %1, %2;" : "=r"(d) : "r"(a), "r"(b));
    return d;
}
__device__ __forceinline__ u64 bf2f2(u32 v) {
    u32 lo = v << 16;
    u32 hi = v & 0xffff0000u;
    u64 r;
    asm("mov.b64 %0, {%1, %2};" : "=l"(r) : "r"(lo), "r"(hi));
    return r;
}
__device__ __forceinline__ u32 f2bf2(float lo, float hi) {
    u32 r;
    asm("cvt.rn.bf16x2.f32 %0, %1, %2;" : "=r"(r) : "f"(hi), "f"(lo)); // d[15:0]=lo (last arg)
    return r;
}
// bf16 mma: D(16x8,f32) = A(16x16,bf16) * B(16x8,bf16) + C
__device__ __forceinline__ void mma_bf16(float &d0, float &d1, float &d2, float &d3,
                                         u32 a0, u32 a1, u32 a2, u32 a3,
                                         u32 b0, u32 b1,
                                         float c0, float c1, float c2, float c3) {
    asm volatile("mma.sync.aligned.m16n8k16.row.col.f32.bf16.bf16.f32 "
                 "{%0,%1,%2,%3}, {%4,%5,%6,%7}, {%8,%9}, {%10,%11,%12,%13};"
                 : "=f"(d0), "=f"(d1), "=f"(d2), "=f"(d3)
                 : "r"(a0), "r"(a1), "r"(a2), "r"(a3), "r"(b0), "r"(b1),
                   "f"(c0), "f"(c1), "f"(c2), "f"(c3));
}
__device__ __forceinline__ void ldmatrix_x4(u32 &r0, u32 &r1, u32 &r2, u32 &r3, u32 saddr) {
    asm volatile("ldmatrix.sync.aligned.m8n8.x4.shared.b16 {%0,%1,%2,%3}, [%4];"
                 : "=r"(r0), "=r"(r1), "=r"(r2), "=r"(r3) : "r"(saddr));
}
__device__ __forceinline__ u32 smem_u32(const void* p) {
    return (u32)__cvta_generic_to_shared(p);
}

// ---------------------------------------------------------------------------
// Kernel 0: dtype probe + zero g_S + init out with b_graph.
// ---------------------------------------------------------------------------
__global__ void detect_and_zero(const void* __restrict__ eraw,
                                const float* __restrict__ bg,
                                float* __restrict__ out) {
    int tid = threadIdx.x; // 1024
    g_S[tid] = 0.f;
    if (tid < NB * OD) out[tid] = bg[tid & (OD - 1)];
    if (tid < 32) {
        const long long* p = (const long long*)eraw;
        long long v0 = p[tid];
        long long v1 = p[64 + tid];
        bool ok = (v0 >= 0 && v0 < NN) && (v1 >= 0 && v1 < NN);
        unsigned m = __ballot_sync(0xffffffffu, ok);
        if (tid == 0) g_is_i64 = (m == 0xffffffffu) ? 1 : 0;
    }
}

// ---------------------------------------------------------------------------
// Kernel 1 (R13-proven, unchanged): YZ = x @ [W_src | W_dst] (+ bias in Y),
// bf16 m16n8k16 mma, double-buffered; bf16 output.
// ---------------------------------------------------------------------------
__global__ __launch_bounds__(256) void node_gemm(const float* __restrict__ x,
                                                 const float* __restrict__ We,
                                                 const float* __restrict__ b_edge) {
    __shared__ __align__(16) u32 As[2][64][12];
    __shared__ __align__(16) u32 Bs[2][8][136];

    const int m0 = blockIdx.y * 64;
    const int n0 = blockIdx.x * 128;
    const int rb = (n0 >= 256) ? 256 : 0;
    const int cb = n0 - rb;
    const int tid = threadIdx.x;
    const int warp = tid >> 5, lane = tid & 31, g = lane >> 2, t = lane & 3;
    const int wm = warp >> 2, wn = warp & 3;

    const int ar = tid >> 2, akp = tid & 3;
    const int bkw = tid >> 5, bn4 = (tid & 31) * 4;

    float acc[2][4][4] = {};

    {
        float4 va = make_float4(0.f, 0.f, 0.f, 0.f);
        if (m0 + ar < NN) va = *(const float4*)(x + (size_t)(m0 + ar) * 256 + akp * 4);
        As[0][ar][akp * 2]     = f2bf2(va.x, va.y);
        As[0][ar][akp * 2 + 1] = f2bf2(va.z, va.w);
        float4 v0 = *(const float4*)(We + (size_t)(rb + 2 * bkw) * 256 + cb + bn4);
        float4 v1 = *(const float4*)(We + (size_t)(rb + 2 * bkw + 1) * 256 + cb + bn4);
        *(uint4*)&Bs[0][bkw][bn4] =
            make_uint4(f2bf2(v0.x, v1.x), f2bf2(v0.y, v1.y), f2bf2(v0.z, v1.z), f2bf2(v0.w, v1.w));
    }

    int p = 0;
    for (int kt = 0; kt < 16; kt++) {
        __syncthreads();
        const int next = kt + 1;
        float4 va, v0, v1;
        if (next < 16) {
            const int k0n = next * 16;
            va = make_float4(0.f, 0.f, 0.f, 0.f);
            if (m0 + ar < NN) va = *(const float4*)(x + (size_t)(m0 + ar) * 256 + k0n + akp * 4);
            v0 = *(const float4*)(We + (size_t)(rb + k0n + 2 * bkw) * 256 + cb + bn4);
            v1 = *(const float4*)(We + (size_t)(rb + k0n + 2 * bkw + 1) * 256 + cb + bn4);
        }

        u32 a[2][4];
        #pragma unroll
        for (int mt = 0; mt < 2; mt++) {
            const u32* rL = As[p][wm * 32 + mt * 16 + g];
            const u32* rH = As[p][wm * 32 + mt * 16 + g + 8];
            a[mt][0] = rL[t];     a[mt][1] = rH[t];
            a[mt][2] = rL[t + 4]; a[mt][3] = rH[t + 4];
        }
        u32 bf[4][2];
        #pragma unroll
        for (int nt = 0; nt < 4; nt++) {
            const int ncol = wn * 32 + nt * 8 + g;
            bf[nt][0] = Bs[p][t][ncol];
            bf[nt][1] = Bs[p][t + 4][ncol];
        }
        #pragma unroll
        for (int mt = 0; mt < 2; mt++)
            #pragma unroll
            for (int nt = 0; nt < 4; nt++)
                mma_bf16(acc[mt][nt][0], acc[mt][nt][1], acc[mt][nt][2], acc[mt][nt][3],
                         a[mt][0], a[mt][1], a[mt][2], a[mt][3],
                         bf[nt][0], bf[nt][1],
                         acc[mt][nt][0], acc[mt][nt][1], acc[mt][nt][2], acc[mt][nt][3]);

        if (next < 16) {
            As[1 - p][ar][akp * 2]     = f2bf2(va.x, va.y);
            As[1 - p][ar][akp * 2 + 1] = f2bf2(va.z, va.w);
            *(uint4*)&Bs[1 - p][bkw][bn4] =
                make_uint4(f2bf2(v0.x, v1.x), f2bf2(v0.y, v1.y), f2bf2(v0.z, v1.z), f2bf2(v0.w, v1.w));
        }
        p ^= 1;
    }

    if (rb == 0) {
        #pragma unroll
        for (int nt = 0; nt < 4; nt++) {
            float2 bb = *(const float2*)(b_edge + n0 + wn * 32 + nt * 8 + 2 * t);
            #pragma unroll
            for (int mt = 0; mt < 2; mt++) {
                acc[mt][nt][0] += bb.x; acc[mt][nt][1] += bb.y;
                acc[mt][nt][2] += bb.x; acc[mt][nt][3] += bb.y;
            }
        }
    }

    #pragma unroll
    for (int mt = 0; mt < 2; mt++) {
        int mrow = m0 + wm * 32 + mt * 16 + g;
        #pragma unroll
        for (int nt = 0; nt < 4; nt++) {
            int colw = (n0 + wn * 32 + nt * 8 + 2 * t) >> 1;
            if (mrow < NN)
                g_YZ[(size_t)mrow * 256 + colw] = f2bf2(acc[mt][nt][0], acc[mt][nt][1]);
            if (mrow + 8 < NN)
                g_YZ[(size_t)(mrow + 8) * 256 + colw] = f2bf2(acc[mt][nt][2], acc[mt][nt][3]);
        }
    }
}

// ---------------------------------------------------------------------------
// Kernel 3 (v12): R14 edge kernel with A-frags loaded via ldmatrix.x4
// (1 instr per (batch,sub) instead of 4 scalar LDS; natural attr layout,
// conflict-free: row addr/16 mod 8 = 3e mod 8, distinct over e=0..7).
// ---------------------------------------------------------------------------
__global__ __launch_bounds__(256, 2) void edge_kernel(const void* __restrict__ eraw,
                                                      const float* __restrict__ attrs,
                                                      const float* __restrict__ We,
                                                      const float* __restrict__ b_edge) {
    __shared__ __align__(16) u32 abf[2][NB][CHUNK][12]; // bf16x2 attr words (natural order)
    __shared__ int idx_s[2][128];                        // [0..63]=src, [64..127]=dst
    __shared__ float Ssh[NB * HID];

    const int tid = threadIdx.x;
    for (int i = tid; i < NB * HID; i += 256) Ssh[i] = 0.f;

    const int warp = tid >> 5, lane = tid & 31, g = lane >> 2, t = lane & 3;
    const int hbase = warp * 32;

    u32 Bf[4][2];
    const int colB = hbase + 8 * (g >> 1) + (g & 1);
    #pragma unroll
    for (int nt = 0; nt < 4; nt++) {
        int col = colB + 2 * nt;
        Bf[nt][0] = f2bf2(We[(512 + 2 * t) * 256 + col],     We[(512 + 2 * t + 1) * 256 + col]);
        Bf[nt][1] = f2bf2(We[(512 + 2 * t + 8) * 256 + col], We[(512 + 2 * t + 9) * 256 + col]);
    }

    const int is64 = g_is_i64;
    const long long* e64 = (const long long*)eraw;
    const int*       e32 = (const int*)eraw;

    const char* yzb = (const char*)g_YZ;
    const u32 co = (u32)(hbase + 8 * t) * 2u;

    const int sb = tid >> 6, eL = tid & 63;

    // ldmatrix lane offset: lanes 0-7 -> rows 0-7 kw0; 8-15 -> rows 8-15 kw0;
    // 16-23 -> rows 0-7 kw1; 24-31 -> rows 8-15 kw1. Row stride 48B, kw 16B.
    const u32 lmoff = (u32)((lane & 15) * 48 + (lane >> 4) * 16);
    const u32 ab0 = smem_u32(&abf[0][0][0][0]) + lmoff;
    const u32 ab1 = smem_u32(&abf[1][0][0][0]) + lmoff;

    u64 acc[NB][4] = {};

    const int nchunks = NE / CHUNK;
    const int stride = gridDim.x;
    int c = blockIdx.x;
    int p = 0;

    {
        const int e0 = c * CHUNK;
        const float4* src = (const float4*)(attrs + ((size_t)sb * NE + e0 + eL) * 16);
        float4 f0 = src[0], f1 = src[1], f2 = src[2], f3 = src[3];
        *(uint4*)&abf[0][sb][eL][0] =
            make_uint4(f2bf2(f0.x, f0.y), f2bf2(f0.z, f0.w), f2bf2(f1.x, f1.y), f2bf2(f1.z, f1.w));
        *(uint4*)&abf[0][sb][eL][4] =
            make_uint4(f2bf2(f2.x, f2.y), f2bf2(f2.z, f2.w), f2bf2(f3.x, f3.y), f2bf2(f3.z, f3.w));
        if (tid < 128) {
            size_t gi = (size_t)(tid >> 6) * NE + e0 + (tid & 63);
            idx_s[0][tid] = is64 ? (int)e64[gi] : e32[gi];
        }
    }

    for (; c < nchunks; c += stride) {
        __syncthreads();   // buffer p staged
        const int cn = c + stride;
        const u32 abase = p ? ab1 : ab0;

        // next chunk's staging loads (covered by this chunk's compute)
        float4 f0, f1, f2, f3;
        int idxR = 0;
        if (cn < nchunks) {
            const int e0n = cn * CHUNK;
            const float4* src = (const float4*)(attrs + ((size_t)sb * NE + e0n + eL) * 16);
            f0 = src[0]; f1 = src[1]; f2 = src[2]; f3 = src[3];
            if (tid < 128) {
                size_t gi = (size_t)(tid >> 6) * NE + e0n + (tid & 63);
                idxR = is64 ? (int)e64[gi] : e32[gi];
            }
        }

        // gather pipeline prologue: sub 0's gathers
        uint4 Gyl, Gyh, Gzl, Gzh;
        {
            const int sl = idx_s[p][g],      dl = idx_s[p][64 + g];
            const int sh = idx_s[p][g + 8],  dh = idx_s[p][64 + g + 8];
            Gyl = *(const uint4*)(yzb + ((u32)sl * 1024u + co));
            Gyh = *(const uint4*)(yzb + ((u32)sh * 1024u + co));
            Gzl = *(const uint4*)(yzb + ((u32)dl * 1024u + 512u + co));
            Gzh = *(const uint4*)(yzb + ((u32)dh * 1024u + 512u + co));
        }

        #pragma unroll
        for (int sub = 0; sub < 4; sub++) {
            // combine base in bf16 domain (frees G registers for next sub)
            u32 pb0 = hadd2bf(Gyl.x, Gzl.x), pb1 = hadd2bf(Gyl.y, Gzl.y);
            u32 pb2 = hadd2bf(Gyl.z, Gzl.z), pb3 = hadd2bf(Gyl.w, Gzl.w);
            u32 ph0 = hadd2bf(Gyh.x, Gzh.x), ph1 = hadd2bf(Gyh.y, Gzh.y);
            u32 ph2 = hadd2bf(Gyh.z, Gzh.z), ph3 = hadd2bf(Gyh.w, Gzh.w);

            // issue next sub's gathers now
            if (sub < 3) {
                const int eb = (sub + 1) * 16;
                const int sl = idx_s[p][eb + g],      dl = idx_s[p][64 + eb + g];
                const int sh = idx_s[p][eb + g + 8],  dh = idx_s[p][64 + eb + g + 8];
                Gyl = *(const uint4*)(yzb + ((u32)sl * 1024u + co));
                Gyh = *(const uint4*)(yzb + ((u32)sh * 1024u + co));
                Gzl = *(const uint4*)(yzb + ((u32)dl * 1024u + 512u + co));
                Gzh = *(const uint4*)(yzb + ((u32)dh * 1024u + 512u + co));
            }

            u64 bLo[4], bHi[4];
            bLo[0] = bf2f2(pb0); bLo[1] = bf2f2(pb1); bLo[2] = bf2f2(pb2); bLo[3] = bf2f2(pb3);
            bHi[0] = bf2f2(ph0); bHi[1] = bf2f2(ph1); bHi[2] = bf2f2(ph2); bHi[3] = bf2f2(ph3);

            const u32 subbase = abase + (u32)(sub * 16 * 48);
            #pragma unroll
            for (int b = 0; b < NB; b++) {
                u32 a0, a1, a2, a3;
                ldmatrix_x4(a0, a1, a2, a3, subbase + (u32)(b * (CHUNK * 48)));
                #pragma unroll
                for (int nt = 0; nt < 4; nt++) {
                    float c0, c1, c2, c3;
                    upk2(bLo[nt], c0, c1);
                    upk2(bHi[nt], c2, c3);
                    float d0, d1, d2, d3;
                    mma_bf16(d0, d1, d2, d3, a0, a1, a2, a3, Bf[nt][0], Bf[nt][1], c0, c1, c2, c3);
                    acc[b][nt] = add2(acc[b][nt], pk2(fmaxf(d0, 0.f), fmaxf(d1, 0.f)));
                    acc[b][nt] = add2(acc[b][nt], pk2(fmaxf(d2, 0.f), fmaxf(d3, 0.f)));
                }
            }
        }

        if (cn < nchunks) {
            *(uint4*)&abf[1 - p][sb][eL][0] =
                make_uint4(f2bf2(f0.x, f0.y), f2bf2(f0.z, f0.w), f2bf2(f1.x, f1.y), f2bf2(f1.z, f1.w));
            *(uint4*)&abf[1 - p][sb][eL][4] =
                make_uint4(f2bf2(f2.x, f2.y), f2bf2(f2.z, f2.w), f2bf2(f3.x, f3.y), f2bf2(f3.z, f3.w));
            if (tid < 128) idx_s[1 - p][tid] = idxR;
        }
        p ^= 1;
    }

    #pragma unroll
    for (int b = 0; b < NB; b++)
        #pragma unroll
        for (int nt = 0; nt < 4; nt++) {
            u64 v = acc[b][nt];
            v = add2(v, __shfl_down_sync(0xffffffffu, v, 16));
            v = add2(v, __shfl_down_sync(0xffffffffu, v, 8));
            v = add2(v, __shfl_down_sync(0xffffffffu, v, 4));
            acc[b][nt] = v;
        }
    if (lane < 4) {
        #pragma unroll
        for (int b = 0; b < NB; b++)
            #pragma unroll
            for (int nt = 0; nt < 4; nt++) {
                float lo, hi;
                upk2(acc[b][nt], lo, hi);
                int h = hbase + 8 * lane + 2 * nt;
                atomicAdd(&Ssh[b * 256 + h], lo);
                atomicAdd(&Ssh[b * 256 + h + 1], hi);
            }
    }
    __syncthreads();
    for (int i = tid; i < NB * HID; i += 256) atomicAdd(&g_S[i], Ssh[i]);
}

// ---------------------------------------------------------------------------
// Kernel 4: out += (S/NE) @ W_graph (out pre-initialized to b_graph).
// ---------------------------------------------------------------------------
__global__ void final_kernel(const float* __restrict__ Wg,
                             float* __restrict__ out) {
    const int b = blockIdx.x >> 3, hc = blockIdx.x & 7;
    const int o = threadIdx.x;
    const float invE = 1.0f / (float)NE;
    float dot = 0.f;
    #pragma unroll
    for (int j = 0; j < 32; j++) {
        int h = hc * 32 + j;
        dot += g_S[b * 256 + h] * Wg[h * 128 + o];
    }
    atomicAdd(&out[b * 128 + o], dot * invE);
}

extern "C" void kernel_launch(void* const* d_in, const int* in_sizes, int n_in,
                              void* d_out, int out_size) {
    const float* x     = (const float*)d_in[0];
    const void*  eidx  = d_in[1];
    const float* attrs = (const float*)d_in[2];
    const float* We    = (const float*)d_in[3];
    const float* be    = (const float*)d_in[4];
    const float* Wg    = (const float*)d_in[5];
    const float* bg    = (const float*)d_in[6];
    float* out = (float*)d_out;

    detect_and_zero<<<1, 1024>>>(eidx, bg, out);
    dim3 gn(4, 313);
    node_gemm<<<gn, 256>>>(x, We, be);
    edge_kernel<<<296, 256>>>(eidx, attrs, We, be);
    final_kernel<<<32, 128>>>(Wg, out);
}

// round 17
// speedup vs baseline: 1.1270x; 1.1270x over previous
#include <cuda_runtime.h>

typedef unsigned long long u64;
typedef unsigned int u32;

#define NN 20000
#define NE 400000
#define NB 4
#define HID 256
#define OD 128
#define CHUNK 64

// YZ table in bf16 pairs: row = 512 bf16 = 256 u32 words = 1024 bytes.
// Y half (cols 0..255) has b_edge folded in.
__device__ __align__(16) u32 g_YZ[NN * 256];
__device__ float g_S[NB * HID];
__device__ int g_is_i64;

__device__ __forceinline__ u64 pk2(float lo, float hi) {
    u64 r;
    asm("mov.b64 %0, {%1, %2};" : "=l"(r) : "r"(__float_as_uint(lo)), "r"(__float_as_uint(hi)));
    return r;
}
__device__ __forceinline__ void upk2(u64 p, float &lo, float &hi) {
    unsigned a, b;
    asm("mov.b64 {%0, %1}, %2;" : "=r"(a), "=r"(b) : "l"(p));
    lo = __uint_as_float(a); hi = __uint_as_float(b);
}
__device__ __forceinline__ u64 add2(u64 a, u64 b) {
    u64 d;
    asm("add.rn.f32x2 %0, %1, %2;" : "=l"(d) : "l"(a), "l"(b));
    return d;
}
__device__ __forceinline__ u32 hadd2bf(u32 a, u32 b) {
    u32 d;
    asm("add.rn.bf16x2 %0, %1, %2;" : "=r"(d) : "r"(a), "r"(b));
    return d;
}
__device__ __forceinline__ u32 f2bf2(float lo, float hi) {
    u32 r;
    asm("cvt.rn.bf16x2.f32 %0, %1, %2;" : "=r"(r) : "f"(hi), "f"(lo)); // d[15:0]=lo (last arg)
    return r;
}
// bf16 mma: D(16x8,f32) = A(16x16,bf16) * B(16x8,bf16) + C
__device__ __forceinline__ void mma_bf16(float &d0, float &d1, float &d2, float &d3,
                                         u32 a0, u32 a1, u32 a2, u32 a3,
                                         u32 b0, u32 b1,
                                         float c0, float c1, float c2, float c3) {
    asm volatile("mma.sync.aligned.m16n8k16.row.col.f32.bf16.bf16.f32 "
                 "{%0,%1,%2,%3}, {%4,%5,%6,%7}, {%8,%9}, {%10,%11,%12,%13};"
                 : "=f"(d0), "=f"(d1), "=f"(d2), "=f"(d3)
                 : "r"(a0), "r"(a1), "r"(a2), "r"(a3), "r"(b0), "r"(b1),
                   "f"(c0), "f"(c1), "f"(c2), "f"(c3));
}

// ---------------------------------------------------------------------------
// Kernel 0: dtype probe + zero g_S + init out with b_graph.
// ---------------------------------------------------------------------------
__global__ void detect_and_zero(const void* __restrict__ eraw,
                                const float* __restrict__ bg,
                                float* __restrict__ out) {
    int tid = threadIdx.x; // 1024
    g_S[tid] = 0.f;
    if (tid < NB * OD) out[tid] = bg[tid & (OD - 1)];
    if (tid < 32) {
        const long long* p = (const long long*)eraw;
        long long v0 = p[tid];
        long long v1 = p[64 + tid];
        bool ok = (v0 >= 0 && v0 < NN) && (v1 >= 0 && v1 < NN);
        unsigned m = __ballot_sync(0xffffffffu, ok);
        if (tid == 0) g_is_i64 = (m == 0xffffffffu) ? 1 : 0;
    }
}

// ---------------------------------------------------------------------------
// Kernel 1 (R13-proven, unchanged): YZ = x @ [W_src | W_dst] (+ bias in Y),
// bf16 m16n8k16 mma, double-buffered; bf16 output.
// ---------------------------------------------------------------------------
__global__ __launch_bounds__(256) void node_gemm(const float* __restrict__ x,
                                                 const float* __restrict__ We,
                                                 const float* __restrict__ b_edge) {
    __shared__ __align__(16) u32 As[2][64][12];
    __shared__ __align__(16) u32 Bs[2][8][136];

    const int m0 = blockIdx.y * 64;
    const int n0 = blockIdx.x * 128;
    const int rb = (n0 >= 256) ? 256 : 0;
    const int cb = n0 - rb;
    const int tid = threadIdx.x;
    const int warp = tid >> 5, lane = tid & 31, g = lane >> 2, t = lane & 3;
    const int wm = warp >> 2, wn = warp & 3;

    const int ar = tid >> 2, akp = tid & 3;
    const int bkw = tid >> 5, bn4 = (tid & 31) * 4;

    float acc[2][4][4] = {};

    {
        float4 va = make_float4(0.f, 0.f, 0.f, 0.f);
        if (m0 + ar < NN) va = *(const float4*)(x + (size_t)(m0 + ar) * 256 + akp * 4);
        As[0][ar][akp * 2]     = f2bf2(va.x, va.y);
        As[0][ar][akp * 2 + 1] = f2bf2(va.z, va.w);
        float4 v0 = *(const float4*)(We + (size_t)(rb + 2 * bkw) * 256 + cb + bn4);
        float4 v1 = *(const float4*)(We + (size_t)(rb + 2 * bkw + 1) * 256 + cb + bn4);
        *(uint4*)&Bs[0][bkw][bn4] =
            make_uint4(f2bf2(v0.x, v1.x), f2bf2(v0.y, v1.y), f2bf2(v0.z, v1.z), f2bf2(v0.w, v1.w));
    }

    int p = 0;
    for (int kt = 0; kt < 16; kt++) {
        __syncthreads();
        const int next = kt + 1;
        float4 va, v0, v1;
        if (next < 16) {
            const int k0n = next * 16;
            va = make_float4(0.f, 0.f, 0.f, 0.f);
            if (m0 + ar < NN) va = *(const float4*)(x + (size_t)(m0 + ar) * 256 + k0n + akp * 4);
            v0 = *(const float4*)(We + (size_t)(rb + k0n + 2 * bkw) * 256 + cb + bn4);
            v1 = *(const float4*)(We + (size_t)(rb + k0n + 2 * bkw + 1) * 256 + cb + bn4);
        }

        u32 a[2][4];
        #pragma unroll
        for (int mt = 0; mt < 2; mt++) {
            const u32* rL = As[p][wm * 32 + mt * 16 + g];
            const u32* rH = As[p][wm * 32 + mt * 16 + g + 8];
            a[mt][0] = rL[t];     a[mt][1] = rH[t];
            a[mt][2] = rL[t + 4]; a[mt][3] = rH[t + 4];
        }
        u32 bf[4][2];
        #pragma unroll
        for (int nt = 0; nt < 4; nt++) {
            const int ncol = wn * 32 + nt * 8 + g;
            bf[nt][0] = Bs[p][t][ncol];
            bf[nt][1] = Bs[p][t + 4][ncol];
        }
        #pragma unroll
        for (int mt = 0; mt < 2; mt++)
            #pragma unroll
            for (int nt = 0; nt < 4; nt++)
                mma_bf16(acc[mt][nt][0], acc[mt][nt][1], acc[mt][nt][2], acc[mt][nt][3],
                         a[mt][0], a[mt][1], a[mt][2], a[mt][3],
                         bf[nt][0], bf[nt][1],
                         acc[mt][nt][0], acc[mt][nt][1], acc[mt][nt][2], acc[mt][nt][3]);

        if (next < 16) {
            As[1 - p][ar][akp * 2]     = f2bf2(va.x, va.y);
            As[1 - p][ar][akp * 2 + 1] = f2bf2(va.z, va.w);
            *(uint4*)&Bs[1 - p][bkw][bn4] =
                make_uint4(f2bf2(v0.x, v1.x), f2bf2(v0.y, v1.y), f2bf2(v0.z, v1.z), f2bf2(v0.w, v1.w));
        }
        p ^= 1;
    }

    if (rb == 0) {
        #pragma unroll
        for (int nt = 0; nt < 4; nt++) {
            float2 bb = *(const float2*)(b_edge + n0 + wn * 32 + nt * 8 + 2 * t);
            #pragma unroll
            for (int mt = 0; mt < 2; mt++) {
                acc[mt][nt][0] += bb.x; acc[mt][nt][1] += bb.y;
                acc[mt][nt][2] += bb.x; acc[mt][nt][3] += bb.y;
            }
        }
    }

    #pragma unroll
    for (int mt = 0; mt < 2; mt++) {
        int mrow = m0 + wm * 32 + mt * 16 + g;
        #pragma unroll
        for (int nt = 0; nt < 4; nt++) {
            int colw = (n0 + wn * 32 + nt * 8 + 2 * t) >> 1;
            if (mrow < NN)
                g_YZ[(size_t)mrow * 256 + colw] = f2bf2(acc[mt][nt][0], acc[mt][nt][1]);
            if (mrow + 8 < NN)
                g_YZ[(size_t)(mrow + 8) * 256 + colw] = f2bf2(acc[mt][nt][2], acc[mt][nt][3]);
        }
    }
}

// ---------------------------------------------------------------------------
// Kernel 3 (v13): R14 edge kernel with direct-float C operands (no u64
// pack/unpack roundtrip for base values). Scalar LDS.32 A-frags, natural
// attr layout, register-pipelined staging, gather pipelining — all as R14.
// ---------------------------------------------------------------------------
__global__ __launch_bounds__(256, 2) void edge_kernel(const void* __restrict__ eraw,
                                                      const float* __restrict__ attrs,
                                                      const float* __restrict__ We,
                                                      const float* __restrict__ b_edge) {
    __shared__ __align__(16) u32 abf[2][NB][CHUNK][12]; // bf16x2 attr words (natural order)
    __shared__ int idx_s[2][128];                        // [0..63]=src, [64..127]=dst
    __shared__ float Ssh[NB * HID];

    const int tid = threadIdx.x;
    for (int i = tid; i < NB * HID; i += 256) Ssh[i] = 0.f;

    const int warp = tid >> 5, lane = tid & 31, g = lane >> 2, t = lane & 3;
    const int hbase = warp * 32;

    u32 Bf[4][2];
    const int colB = hbase + 8 * (g >> 1) + (g & 1);
    #pragma unroll
    for (int nt = 0; nt < 4; nt++) {
        int col = colB + 2 * nt;
        Bf[nt][0] = f2bf2(We[(512 + 2 * t) * 256 + col],     We[(512 + 2 * t + 1) * 256 + col]);
        Bf[nt][1] = f2bf2(We[(512 + 2 * t + 8) * 256 + col], We[(512 + 2 * t + 9) * 256 + col]);
    }

    const int is64 = g_is_i64;
    const long long* e64 = (const long long*)eraw;
    const int*       e32 = (const int*)eraw;

    const char* yzb = (const char*)g_YZ;
    const u32 co = (u32)(hbase + 8 * t) * 2u;

    const int sb = tid >> 6, eL = tid & 63;

    u64 acc[NB][4] = {};

    const int nchunks = NE / CHUNK;
    const int stride = gridDim.x;
    int c = blockIdx.x;
    int p = 0;

    {
        const int e0 = c * CHUNK;
        const float4* src = (const float4*)(attrs + ((size_t)sb * NE + e0 + eL) * 16);
        float4 f0 = src[0], f1 = src[1], f2 = src[2], f3 = src[3];
        *(uint4*)&abf[0][sb][eL][0] =
            make_uint4(f2bf2(f0.x, f0.y), f2bf2(f0.z, f0.w), f2bf2(f1.x, f1.y), f2bf2(f1.z, f1.w));
        *(uint4*)&abf[0][sb][eL][4] =
            make_uint4(f2bf2(f2.x, f2.y), f2bf2(f2.z, f2.w), f2bf2(f3.x, f3.y), f2bf2(f3.z, f3.w));
        if (tid < 128) {
            size_t gi = (size_t)(tid >> 6) * NE + e0 + (tid & 63);
            idx_s[0][tid] = is64 ? (int)e64[gi] : e32[gi];
        }
    }

    for (; c < nchunks; c += stride) {
        __syncthreads();   // buffer p staged
        const int cn = c + stride;

        // next chunk's staging loads (covered by this chunk's compute)
        float4 f0, f1, f2, f3;
        int idxR = 0;
        if (cn < nchunks) {
            const int e0n = cn * CHUNK;
            const float4* src = (const float4*)(attrs + ((size_t)sb * NE + e0n + eL) * 16);
            f0 = src[0]; f1 = src[1]; f2 = src[2]; f3 = src[3];
            if (tid < 128) {
                size_t gi = (size_t)(tid >> 6) * NE + e0n + (tid & 63);
                idxR = is64 ? (int)e64[gi] : e32[gi];
            }
        }

        // gather pipeline prologue: sub 0's gathers
        uint4 Gyl, Gyh, Gzl, Gzh;
        {
            const int sl = idx_s[p][g],      dl = idx_s[p][64 + g];
            const int sh = idx_s[p][g + 8],  dh = idx_s[p][64 + g + 8];
            Gyl = *(const uint4*)(yzb + ((u32)sl * 1024u + co));
            Gyh = *(const uint4*)(yzb + ((u32)sh * 1024u + co));
            Gzl = *(const uint4*)(yzb + ((u32)dl * 1024u + 512u + co));
            Gzh = *(const uint4*)(yzb + ((u32)dh * 1024u + 512u + co));
        }

        #pragma unroll
        for (int sub = 0; sub < 4; sub++) {
            // combine base in bf16 domain, then expand DIRECTLY to floats
            // (no u64 pack/unpack; values reused across all 4 batches)
            u32 q;
            float cl0[4], cl1[4], ch0[4], ch1[4];
            q = hadd2bf(Gyl.x, Gzl.x); cl0[0] = __uint_as_float(q << 16); cl1[0] = __uint_as_float(q & 0xffff0000u);
            q = hadd2bf(Gyl.y, Gzl.y); cl0[1] = __uint_as_float(q << 16); cl1[1] = __uint_as_float(q & 0xffff0000u);
            q = hadd2bf(Gyl.z, Gzl.z); cl0[2] = __uint_as_float(q << 16); cl1[2] = __uint_as_float(q & 0xffff0000u);
            q = hadd2bf(Gyl.w, Gzl.w); cl0[3] = __uint_as_float(q << 16); cl1[3] = __uint_as_float(q & 0xffff0000u);
            q = hadd2bf(Gyh.x, Gzh.x); ch0[0] = __uint_as_float(q << 16); ch1[0] = __uint_as_float(q & 0xffff0000u);
            q = hadd2bf(Gyh.y, Gzh.y); ch0[1] = __uint_as_float(q << 16); ch1[1] = __uint_as_float(q & 0xffff0000u);
            q = hadd2bf(Gyh.z, Gzh.z); ch0[2] = __uint_as_float(q << 16); ch1[2] = __uint_as_float(q & 0xffff0000u);
            q = hadd2bf(Gyh.w, Gzh.w); ch0[3] = __uint_as_float(q << 16); ch1[3] = __uint_as_float(q & 0xffff0000u);

            // issue next sub's gathers now
            if (sub < 3) {
                const int eb = (sub + 1) * 16;
                const int sl = idx_s[p][eb + g],      dl = idx_s[p][64 + eb + g];
                const int sh = idx_s[p][eb + g + 8],  dh = idx_s[p][64 + eb + g + 8];
                Gyl = *(const uint4*)(yzb + ((u32)sl * 1024u + co));
                Gyh = *(const uint4*)(yzb + ((u32)sh * 1024u + co));
                Gzl = *(const uint4*)(yzb + ((u32)dl * 1024u + 512u + co));
                Gzh = *(const uint4*)(yzb + ((u32)dh * 1024u + 512u + co));
            }

            const int eb = sub * 16;
            #pragma unroll
            for (int b = 0; b < NB; b++) {
                const u32* arL = abf[p][b][eb + g];
                const u32* arH = abf[p][b][eb + g + 8];
                u32 a0 = arL[t],     a1 = arH[t];
                u32 a2 = arL[t + 4], a3 = arH[t + 4];
                #pragma unroll
                for (int nt = 0; nt < 4; nt++) {
                    float d0, d1, d2, d3;
                    mma_bf16(d0, d1, d2, d3, a0, a1, a2, a3, Bf[nt][0], Bf[nt][1],
                             cl0[nt], cl1[nt], ch0[nt], ch1[nt]);
                    acc[b][nt] = add2(acc[b][nt], pk2(fmaxf(d0, 0.f), fmaxf(d1, 0.f)));
                    acc[b][nt] = add2(acc[b][nt], pk2(fmaxf(d2, 0.f), fmaxf(d3, 0.f)));
                }
            }
        }

        if (cn < nchunks) {
            *(uint4*)&abf[1 - p][sb][eL][0] =
                make_uint4(f2bf2(f0.x, f0.y), f2bf2(f0.z, f0.w), f2bf2(f1.x, f1.y), f2bf2(f1.z, f1.w));
            *(uint4*)&abf[1 - p][sb][eL][4] =
                make_uint4(f2bf2(f2.x, f2.y), f2bf2(f2.z, f2.w), f2bf2(f3.x, f3.y), f2bf2(f3.z, f3.w));
            if (tid < 128) idx_s[1 - p][tid] = idxR;
        }
        p ^= 1;
    }

    #pragma unroll
    for (int b = 0; b < NB; b++)
        #pragma unroll
        for (int nt = 0; nt < 4; nt++) {
            u64 v = acc[b][nt];
            v = add2(v, __shfl_down_sync(0xffffffffu, v, 16));
            v = add2(v, __shfl_down_sync(0xffffffffu, v, 8));
            v = add2(v, __shfl_down_sync(0xffffffffu, v, 4));
            acc[b][nt] = v;
        }
    if (lane < 4) {
        #pragma unroll
        for (int b = 0; b < NB; b++)
            #pragma unroll
            for (int nt = 0; nt < 4; nt++) {
                float lo, hi;
                upk2(acc[b][nt], lo, hi);
                int h = hbase + 8 * lane + 2 * nt;
                atomicAdd(&Ssh[b * 256 + h], lo);
                atomicAdd(&Ssh[b * 256 + h + 1], hi);
            }
    }
    __syncthreads();
    for (int i = tid; i < NB * HID; i += 256) atomicAdd(&g_S[i], Ssh[i]);
}

// ---------------------------------------------------------------------------
// Kernel 4: out += (S/NE) @ W_graph (out pre-initialized to b_graph).
// ---------------------------------------------------------------------------
__global__ void final_kernel(const float* __restrict__ Wg,
                             float* __restrict__ out) {
    const int b = blockIdx.x >> 3, hc = blockIdx.x & 7;
    const int o = threadIdx.x;
    const float invE = 1.0f / (float)NE;
    float dot = 0.f;
    #pragma unroll
    for (int j = 0; j < 32; j++) {
        int h = hc * 32 + j;
        dot += g_S[b * 256 + h] * Wg[h * 128 + o];
    }
    atomicAdd(&out[b * 128 + o], dot * invE);
}

extern "C" void kernel_launch(void* const* d_in, const int* in_sizes, int n_in,
                              void* d_out, int out_size) {
    const float* x     = (const float*)d_in[0];
    const void*  eidx  = d_in[1];
    const float* attrs = (const float*)d_in[2];
    const float* We    = (const float*)d_in[3];
    const float* be    = (const float*)d_in[4];
    const float* Wg    = (const float*)d_in[5];
    const float* bg    = (const float*)d_in[6];
    float* out = (float*)d_out;

    detect_and_zero<<<1, 1024>>>(eidx, bg, out);
    dim3 gn(4, 313);
    node_gemm<<<gn, 256>>>(x, We, be);
    edge_kernel<<<304, 256>>>(eidx, attrs, We, be);  // 2 x 152 SMs (GB300)
    final_kernel<<<32, 128>>>(Wg, out);
}